// round 1
// baseline (speedup 1.0000x reference)
#include <cuda_runtime.h>
#include <math.h>

// Problem constants
#define BB   16
#define LL   50
#define BL   800      // B*L
#define DD   8
#define HH   128
#define NCAT 1000
#define NIT  8192
#define BD   128      // B*D

// Output layout (flat float32, tuple order)
#define OFF_CATGY 0           // (16,8,1000) = 128000
#define OFF_DSC   128000      // (B,D,L) reshape of (B,L,D) = 6400, flat order (b,l,d)
#define OFF_DCAND 134400      // (16,8,8192) = 1048576
#define OFF_EMB   1182976     // (16,50,128) = 102400
#define OFF_ECAND 1285376     // (8192,128)  = 1048576
#define OFF_LOSS  2333952     // scalar

// Scratch (no cudaMalloc allowed)
__device__ float g_hd [BL * 1024];   // emb @ Wd
__device__ float g_hk [BL * HH];     // emb @ Wk + bk
__device__ float g_hkc[NIT * HH];    // emb_cand @ Wk + bk
__device__ float g_pkc[NIT * HH];    // hkc @ Wk1
__device__ float g_agg[BD * HH];     // logsumexp result (row = b*8+d)
__device__ float g_pd [BD * HH];     // agg @ Wd1 + b1
__device__ float g_pk [BL * HH];     // hk @ Wk1

// ---------------------------------------------------------------------------
// Gather: emb and emb_cand straight into the output buffer (float4 per thread)
// ---------------------------------------------------------------------------
__global__ void gather_kernel(const int* __restrict__ inp,
                              const int* __restrict__ cand,
                              const float* __restrict__ table,
                              float* __restrict__ out) {
    int i = blockIdx.x * blockDim.x + threadIdx.x;
    const int total = (BL + NIT) * 32;          // float4 slots
    if (i >= total) return;
    int row = i >> 5, k4 = i & 31;
    const float4* t4 = (const float4*)table;
    float4* dst;
    int idx;
    if (row < BL) {
        idx = inp[row];
        dst = (float4*)(out + OFF_EMB) + row * 32;
    } else {
        row -= BL;
        idx = cand[row];
        dst = (float4*)(out + OFF_ECAND) + row * 32;
    }
    dst[k4] = t4[idx * 32 + k4];
}

// ---------------------------------------------------------------------------
// Generic fp32 GEMM for K=128: C[M,N] = A[M,128] @ B[128,N] (+ bias)
// Block tile 64x64, 256 threads, 4x4 micro-tile, full-K staged in SMEM.
// ---------------------------------------------------------------------------
__global__ void gemm_k128(const float* __restrict__ A,
                          const float* __restrict__ Bm,
                          const float* __restrict__ bias,
                          float* __restrict__ C,
                          int M, int N) {
    __shared__ float As[64][132];
    __shared__ float Bs[128][68];
    const int bm = blockIdx.y * 64, bn = blockIdx.x * 64;
    const int tid = threadIdx.x;

    // A tile: 64 rows x 128 k, float4
    for (int i = tid; i < 64 * 32; i += 256) {
        int r = i >> 5, k4 = (i & 31) * 4;
        float4 v = make_float4(0.f, 0.f, 0.f, 0.f);
        if (bm + r < M) v = *(const float4*)(A + (size_t)(bm + r) * 128 + k4);
        *(float4*)&As[r][k4] = v;
    }
    // B tile: 128 k x 64 cols (guarded for N=1000)
    for (int i = tid; i < 128 * 16; i += 256) {
        int k = i >> 4, c4 = (i & 15) * 4;
        int c = bn + c4;
        const float* brow = Bm + (size_t)k * N;
        float4 v = make_float4(0.f, 0.f, 0.f, 0.f);
        if (c + 3 < N) v = *(const float4*)(brow + c);
        else {
            if (c     < N) v.x = brow[c];
            if (c + 1 < N) v.y = brow[c + 1];
            if (c + 2 < N) v.z = brow[c + 2];
        }
        *(float4*)&Bs[k][c4] = v;
    }
    __syncthreads();

    const int tx = tid & 15, ty = tid >> 4;
    float acc[4][4];
#pragma unroll
    for (int i = 0; i < 4; i++)
#pragma unroll
        for (int j = 0; j < 4; j++) acc[i][j] = 0.f;

#pragma unroll 4
    for (int k = 0; k < 128; k++) {
        float a[4], b[4];
#pragma unroll
        for (int i = 0; i < 4; i++) a[i] = As[ty * 4 + i][k];
#pragma unroll
        for (int j = 0; j < 4; j++) b[j] = Bs[k][tx * 4 + j];
#pragma unroll
        for (int i = 0; i < 4; i++)
#pragma unroll
            for (int j = 0; j < 4; j++)
                acc[i][j] = fmaf(a[i], b[j], acc[i][j]);
    }

#pragma unroll
    for (int i = 0; i < 4; i++) {
        int r = bm + ty * 4 + i;
        if (r >= M) break;
#pragma unroll
        for (int j = 0; j < 4; j++) {
            int c = bn + tx * 4 + j;
            if (c < N) {
                float bv = bias ? bias[c] : 0.f;
                C[(size_t)r * N + c] = acc[i][j] + bv;
            }
        }
    }
}

// ---------------------------------------------------------------------------
// logsumexp over L=50: agg[b, j] = LSE_l hd[(b*50+l)*1024 + j]
// ---------------------------------------------------------------------------
__global__ void lse_kernel(const float* __restrict__ hd, float* __restrict__ agg) {
    int b = blockIdx.x;
    int j = blockIdx.y * 256 + threadIdx.x;
    const float* base = hd + (size_t)b * LL * 1024 + j;
    float m = -INFINITY;
#pragma unroll 5
    for (int l = 0; l < LL; l++) m = fmaxf(m, base[l * 1024]);
    float s = 0.f;
#pragma unroll 5
    for (int l = 0; l < LL; l++) s += expf(base[l * 1024] - m);
    agg[b * 1024 + j] = m + logf(s);
}

// ---------------------------------------------------------------------------
// demand_sim_loss: hn = agg/(||agg||+1e-12); loss = sum_b(||sum_d hn||^2 - sum_d||hn||^2)/896
// ---------------------------------------------------------------------------
__global__ void finalize_kernel(const float* __restrict__ agg, float* __restrict__ out) {
    __shared__ float inv[128];
    __shared__ float red[128];
    int tid = threadIdx.x;  // 128 threads
    {
        const float* a = agg + tid * 128;
        float s = 0.f;
#pragma unroll 8
        for (int h = 0; h < 128; h++) s = fmaf(a[h], a[h], s);
        inv[tid] = 1.f / (sqrtf(s) + 1e-12f);
    }
    __syncthreads();
    float accv = 0.f;
    int h = tid;
    for (int b = 0; b < BB; b++) {
        float sv = 0.f, sq = 0.f;
#pragma unroll
        for (int d = 0; d < DD; d++) {
            int bd = b * DD + d;
            float x = agg[bd * 128 + h] * inv[bd];
            sv += x;
            sq = fmaf(x, x, sq);
        }
        accv += sv * sv - sq;
    }
    red[tid] = accv;
    __syncthreads();
    if (tid == 0) {
        float t = 0.f;
        for (int i = 0; i < 128; i++) t += red[i];
        out[OFF_LOSS] = t / 896.f;   // B*D*(D-1)
    }
}

// ---------------------------------------------------------------------------
// demand_score: one warp per (b,l,d) output; sum_h relu(pd'+pk)*w
// ---------------------------------------------------------------------------
__global__ void dscore_kernel(const float* __restrict__ pd,
                              const float* __restrict__ pk,
                              const float* __restrict__ w,
                              float* __restrict__ out) {
    int wid  = (blockIdx.x * blockDim.x + threadIdx.x) >> 5;
    int lane = threadIdx.x & 31;
    if (wid >= BB * LL * DD) return;
    int b = wid / (LL * DD);
    int rem = wid % (LL * DD);
    int l = rem / DD, d = rem & (DD - 1);
    const float4* p4 = (const float4*)(pd + (b * DD + d) * 128);
    const float4* k4 = (const float4*)(pk + (b * LL + l) * 128);
    const float4* w4 = (const float4*)w;
    float4 a = p4[lane], c = k4[lane], ww = w4[lane];
    float acc = fmaxf(a.x + c.x, 0.f) * ww.x
              + fmaxf(a.y + c.y, 0.f) * ww.y
              + fmaxf(a.z + c.z, 0.f) * ww.z
              + fmaxf(a.w + c.w, 0.f) * ww.w;
#pragma unroll
    for (int o = 16; o > 0; o >>= 1) acc += __shfl_down_sync(0xffffffffu, acc, o);
    if (lane == 0) out[OFF_DSC + b * (LL * DD) + l * DD + d] = acc;
}

// ---------------------------------------------------------------------------
// demand_score_candidate: "relu-GEMM"
// out[bd, item] = sum_h relu(pd'[bd,h] + pkc[item,h]) * w[h]
// Block: 64 bd x 64 items, 256 threads, 4x4 micro, full-K in SMEM.
// ---------------------------------------------------------------------------
__global__ void cand_kernel(const float* __restrict__ pd,
                            const float* __restrict__ pkc,
                            const float* __restrict__ w,
                            float* __restrict__ out) {
    __shared__ float Ps[64][132];
    __shared__ float Qs[64][132];
    __shared__ float ws[128];
    const int itb = blockIdx.x * 64, bdb = blockIdx.y * 64;
    const int tid = threadIdx.x;

    for (int i = tid; i < 64 * 32; i += 256) {
        int r = i >> 5, k4 = (i & 31) * 4;
        *(float4*)&Ps[r][k4] = *(const float4*)(pd  + (size_t)(bdb + r) * 128 + k4);
        *(float4*)&Qs[r][k4] = *(const float4*)(pkc + (size_t)(itb + r) * 128 + k4);
    }
    if (tid < 128) ws[tid] = w[tid];
    __syncthreads();

    const int tx = tid & 15, ty = tid >> 4;
    float acc[4][4];
#pragma unroll
    for (int i = 0; i < 4; i++)
#pragma unroll
        for (int j = 0; j < 4; j++) acc[i][j] = 0.f;

#pragma unroll 4
    for (int k = 0; k < 128; k++) {
        float wv = ws[k];
        float a[4], q[4];
#pragma unroll
        for (int i = 0; i < 4; i++) a[i] = Ps[ty * 4 + i][k];
#pragma unroll
        for (int j = 0; j < 4; j++) q[j] = Qs[tx * 4 + j][k];
#pragma unroll
        for (int i = 0; i < 4; i++)
#pragma unroll
            for (int j = 0; j < 4; j++)
                acc[i][j] = fmaf(fmaxf(a[i] + q[j], 0.f), wv, acc[i][j]);
    }

#pragma unroll
    for (int i = 0; i < 4; i++) {
        int r = bdb + ty * 4 + i;
#pragma unroll
        for (int j = 0; j < 4; j++) {
            int c = itb + tx * 4 + j;
            out[OFF_DCAND + (size_t)r * NIT + c] = acc[i][j];
        }
    }
}

// ---------------------------------------------------------------------------
extern "C" void kernel_launch(void* const* d_in, const int* in_sizes, int n_in,
                              void* d_out, int out_size) {
    const int*   input = (const int*)d_in[0];
    const int*   cand  = (const int*)d_in[1];
    // d_in[2] session_last_catgy_index, d_in[3] mask_catgy: unused by reference
    const float* table = (const float*)d_in[4];
    const float* Wd    = (const float*)d_in[5];
    const float* Wk    = (const float*)d_in[6];
    const float* bk    = (const float*)d_in[7];
    const float* W1    = (const float*)d_in[8];
    const float* b1    = (const float*)d_in[9];
    const float* wsc   = (const float*)d_in[10];
    const float* Wc    = (const float*)d_in[11];
    const float* bc    = (const float*)d_in[12];
    float* out = (float*)d_out;

    float *hd, *hk, *hkc, *pkc, *agg, *pd, *pk;
    cudaGetSymbolAddress((void**)&hd,  g_hd);
    cudaGetSymbolAddress((void**)&hk,  g_hk);
    cudaGetSymbolAddress((void**)&hkc, g_hkc);
    cudaGetSymbolAddress((void**)&pkc, g_pkc);
    cudaGetSymbolAddress((void**)&agg, g_agg);
    cudaGetSymbolAddress((void**)&pd,  g_pd);
    cudaGetSymbolAddress((void**)&pk,  g_pk);

    const float* Wd1 = W1;              // W1[:128]
    const float* Wk1 = W1 + 128 * 128;  // W1[128:]

    // 1) gathers (emb, emb_cand into output buffer)
    {
        int total = (BL + NIT) * 32;
        gather_kernel<<<(total + 255) / 256, 256>>>(input, cand, table, out);
    }
    // 2) hidden_key = emb @ Wk + bk            (800 x 128)
    gemm_k128<<<dim3(2, 13), 256>>>(out + OFF_EMB, Wk, bk, hk, BL, 128);
    // 3) hidden_demand = emb @ Wd              (800 x 1024)
    gemm_k128<<<dim3(16, 13), 256>>>(out + OFF_EMB, Wd, nullptr, hd, BL, 1024);
    // 4) hidden_key_cand = emb_cand @ Wk + bk  (8192 x 128)
    gemm_k128<<<dim3(2, 128), 256>>>(out + OFF_ECAND, Wk, bk, hkc, NIT, 128);
    // 5) pkc = hkc @ Wk1                       (8192 x 128)
    gemm_k128<<<dim3(2, 128), 256>>>(hkc, Wk1, nullptr, pkc, NIT, 128);
    // 6) agg = logsumexp_l(hd)                 (16 x 1024) == (128 x 128)
    lse_kernel<<<dim3(BB, 4), 256>>>(hd, agg);
    // 7) catgy_score = agg @ Wc + bc           (128 x 1000) -> output
    gemm_k128<<<dim3(16, 2), 256>>>(agg, Wc, bc, out + OFF_CATGY, BD, NCAT);
    // 8) pd' = agg @ Wd1 + b1                  (128 x 128)  (b1 folded in)
    gemm_k128<<<dim3(2, 2), 256>>>(agg, Wd1, b1, pd, BD, 128);
    // 9) pk = hidden_key @ Wk1                 (800 x 128)
    gemm_k128<<<dim3(2, 13), 256>>>(hk, Wk1, nullptr, pk, BL, 128);
    // 10) demand_sim_loss -> output scalar
    finalize_kernel<<<1, 128>>>(agg, out);
    // 11) demand_score -> output (flat (b,l,d) order)
    dscore_kernel<<<800, 256>>>(pd, pk, wsc, out);
    // 12) demand_score_candidate -> output
    cand_kernel<<<dim3(NIT / 64, 2), 256>>>(pd, pkc, wsc, out);
}

// round 2
// speedup vs baseline: 1.5436x; 1.5436x over previous
#include <cuda_runtime.h>
#include <math.h>

typedef unsigned long long u64;

// ---- problem constants ----
#define BL    800       // B*L
#define NIT   8192
#define NROW  8992      // BL + NIT

// ---- output layout (flat float32, tuple order) ----
#define OFF_CATGY 0           // (16,8,1000)
#define OFF_DSC   128000      // (16,8,50) flat == (b,l,d)
#define OFF_DCAND 134400      // (16,8,8192)
#define OFF_EMB   1182976     // (16,50,128)
#define OFF_ECAND 1285376     // (8192,128)
#define OFF_LOSS  2333952     // scalar

// ---- scratch (__device__ globals; no cudaMalloc allowed) ----
__device__ float g_wf  [128 * 128];     // Wk @ Wk1
__device__ float g_bf  [128];           // bk @ Wk1
__device__ float g_agg [128 * 128];     // [bd][h]
__device__ float g_pd  [128 * 128];     // agg @ Wd1 + b1, [bd][h]
__device__ float g_pdT [128 * 128];     // transposed [h][bd]
__device__ float g_pk  [BL * 128];      // [row][h]
__device__ float g_pkcT[128 * NIT];     // transposed [h][item]

// ---- f32x2 helpers (sm_103a packed fp32) ----
union F4U { float4 f; u64 u[2]; float s[4]; };

__device__ __forceinline__ u64 pack2(float lo, float hi) {
    u64 r; asm("mov.b64 %0, {%1,%2};" : "=l"(r) : "f"(lo), "f"(hi)); return r;
}
__device__ __forceinline__ void unpack2(u64 v, float& lo, float& hi) {
    asm("mov.b64 {%0,%1}, %2;" : "=f"(lo), "=f"(hi) : "l"(v));
}
__device__ __forceinline__ u64 fma2(u64 a, u64 b, u64 c) {
    u64 r; asm("fma.rn.f32x2 %0, %1, %2, %3;" : "=l"(r) : "l"(a), "l"(b), "l"(c)); return r;
}
__device__ __forceinline__ u64 add2(u64 a, u64 b) {
    u64 r; asm("add.rn.f32x2 %0, %1, %2;" : "=l"(r) : "l"(a), "l"(b)); return r;
}
__device__ __forceinline__ u64 relu2(u64 v) {
    float a, b; unpack2(v, a, b);
    a = fmaxf(a, 0.f); b = fmaxf(b, 0.f);
    return pack2(a, b);
}

// ===========================================================================
// K1: gather emb/emb_cand into output  +  fold Wf = Wk@Wk1, bf = bk@Wk1
// ===========================================================================
__global__ void k1_prep(const int* __restrict__ inp, const int* __restrict__ cand,
                        const float* __restrict__ table,
                        const float* __restrict__ Wk, const float* __restrict__ Wk1,
                        const float* __restrict__ bk,
                        float* __restrict__ out,
                        float* __restrict__ wf, float* __restrict__ bf) {
    __shared__ float srow[256];
    int bx = blockIdx.x, tid = threadIdx.x;
    if (bx < 1124) {                       // gather: 8992 rows x 32 float4
        int i = bx * 256 + tid;
        if (i >= NROW * 32) return;
        int row = i >> 5, k4 = i & 31;
        const float4* t4 = (const float4*)table;
        float4* dst; int idx;
        if (row < BL) { idx = inp[row];        dst = (float4*)(out + OFF_EMB)   + row * 32; }
        else          { idx = cand[row - BL];  dst = (float4*)(out + OFF_ECAND) + (row - BL) * 32; }
        dst[k4] = t4[idx * 32 + k4];
    } else if (bx < 1188) {                // Wf rows: 64 blocks x 2 rows
        int i0 = (bx - 1124) * 2;
        srow[tid] = Wk[i0 * 128 + tid];    // rows i0, i0+1
        __syncthreads();
        int local = tid >> 7;              // 0 or 1
        int j = tid & 127;
        const float* wr = &srow[local * 128];
        float acc = 0.f;
#pragma unroll 8
        for (int h = 0; h < 128; h++)
            acc = fmaf(wr[h], __ldg(Wk1 + h * 128 + j), acc);
        wf[(i0 + local) * 128 + j] = acc;
    } else {                               // bf
        if (tid < 128) srow[tid] = bk[tid];
        __syncthreads();
        if (tid < 128) {
            float acc = 0.f;
#pragma unroll 8
            for (int h = 0; h < 128; h++)
                acc = fmaf(srow[h], __ldg(Wk1 + h * 128 + tid), acc);
            bf[tid] = acc;
        }
    }
}

// ===========================================================================
// K2: fused emb@Wd + logsumexp over L  ->  agg[bd][h]
// grid (cb=8, b=16); block 256.  k-major A tile, f32x2 FFMA.
// ===========================================================================
__global__ void k2_embwd_lse(const float* __restrict__ emb_all,
                             const float* __restrict__ Wd,
                             float* __restrict__ agg) {
    __shared__ __align__(16) float As[128][68];   // [k][l], l padded to 64
    __shared__ __align__(16) float Bs[128][132];  // [k][j]
    __shared__ float red[8][132];
    int cb = blockIdx.x, b = blockIdx.y, tid = threadIdx.x;
    const float* embB = emb_all + b * 6400;

    for (int idx = tid; idx < 64 * 32; idx += 256) {   // A transpose-load
        int l = idx & 63, k4 = idx >> 6;
        float4 v = make_float4(0.f, 0.f, 0.f, 0.f);
        if (l < 50) v = *(const float4*)(embB + l * 128 + k4 * 4);
        As[k4 * 4 + 0][l] = v.x; As[k4 * 4 + 1][l] = v.y;
        As[k4 * 4 + 2][l] = v.z; As[k4 * 4 + 3][l] = v.w;
    }
    for (int idx = tid; idx < 128 * 32; idx += 256) {  // Wd col-slab
        int k = idx >> 5, j4 = idx & 31;
        *(float4*)&Bs[k][j4 * 4] = *(const float4*)(Wd + k * 1024 + cb * 128 + j4 * 4);
    }
    __syncthreads();

    int tx = tid & 31, ty = tid >> 5;     // cols tx*4..+3, rows l = ty*8..+7
    u64 acc[8][2];
#pragma unroll
    for (int i = 0; i < 8; i++) { acc[i][0] = 0ull; acc[i][1] = 0ull; }

#pragma unroll 4
    for (int k = 0; k < 128; k++) {
        F4U q;  q.f  = *(const float4*)&Bs[k][tx * 4];
        F4U a0; a0.f = *(const float4*)&As[k][ty * 8];
        F4U a1; a1.f = *(const float4*)&As[k][ty * 8 + 4];
#pragma unroll
        for (int i = 0; i < 8; i++) {
            float av = (i < 4) ? a0.s[i] : a1.s[i - 4];
            u64 a2 = pack2(av, av);
            acc[i][0] = fma2(a2, q.u[0], acc[i][0]);
            acc[i][1] = fma2(a2, q.u[1], acc[i][1]);
        }
    }

    // logsumexp over l (valid rows only)
    int nval = 50 - ty * 8; if (nval > 8) nval = 8; if (nval < 0) nval = 0;
    float vals[8][4];
#pragma unroll
    for (int i = 0; i < 8; i++) {
        unpack2(acc[i][0], vals[i][0], vals[i][1]);
        unpack2(acc[i][1], vals[i][2], vals[i][3]);
    }
    float m[4];
#pragma unroll
    for (int u = 0; u < 4; u++) {
        float mm = -INFINITY;
        for (int i = 0; i < nval; i++) mm = fmaxf(mm, vals[i][u]);
        m[u] = mm;
        red[ty][tx * 4 + u] = mm;
    }
    __syncthreads();
    float M[4];
#pragma unroll
    for (int u = 0; u < 4; u++) {
        float mm = -INFINITY;
#pragma unroll
        for (int t = 0; t < 8; t++) mm = fmaxf(mm, red[t][tx * 4 + u]);
        M[u] = mm;
    }
    __syncthreads();
#pragma unroll
    for (int u = 0; u < 4; u++) {
        float s = 0.f;
        for (int i = 0; i < nval; i++) s += expf(vals[i][u] - M[u]);
        red[ty][tx * 4 + u] = s;
    }
    __syncthreads();
    if (ty == 0) {
#pragma unroll
        for (int u = 0; u < 4; u++) {
            float S = 0.f;
#pragma unroll
            for (int t = 0; t < 8; t++) S += red[t][tx * 4 + u];
            agg[b * 1024 + cb * 128 + tx * 4 + u] = M[u] + logf(S);
        }
    }
}

// ===========================================================================
// K3: pk (rows<800) and pkcT (rows>=800) = rows @ Wf + bf
// tile 64 rows x 128 cols; k-major A; f32x2.
// ===========================================================================
__global__ void k3_pkgemm(const float* __restrict__ out_emb_base,
                          const float* __restrict__ wf, const float* __restrict__ bf,
                          float* __restrict__ pk, float* __restrict__ pkcT) {
    __shared__ __align__(16) float As[128][68];
    __shared__ __align__(16) float Bs[128][132];
    int bm = blockIdx.x * 64, tid = threadIdx.x;
    const float* emb  = out_emb_base + OFF_EMB;
    const float* ecnd = out_emb_base + OFF_ECAND;

    for (int idx = tid; idx < 64 * 32; idx += 256) {
        int r = idx & 63, k4 = idx >> 6;
        int row = bm + r;
        float4 v = make_float4(0.f, 0.f, 0.f, 0.f);
        if (row < BL)        v = *(const float4*)(emb  + row * 128 + k4 * 4);
        else if (row < NROW) v = *(const float4*)(ecnd + (row - BL) * 128 + k4 * 4);
        As[k4 * 4 + 0][r] = v.x; As[k4 * 4 + 1][r] = v.y;
        As[k4 * 4 + 2][r] = v.z; As[k4 * 4 + 3][r] = v.w;
    }
    for (int idx = tid; idx < 128 * 32; idx += 256) {
        int k = idx >> 5, j4 = idx & 31;
        *(float4*)&Bs[k][j4 * 4] = *(const float4*)(wf + k * 128 + j4 * 4);
    }
    __syncthreads();

    int tx = tid & 31, ty = tid >> 5;   // cols tx*4, rows ty*8..+7
    u64 acc[8][2];
#pragma unroll
    for (int i = 0; i < 8; i++) { acc[i][0] = 0ull; acc[i][1] = 0ull; }

#pragma unroll 4
    for (int k = 0; k < 128; k++) {
        F4U q;  q.f  = *(const float4*)&Bs[k][tx * 4];
        F4U a0; a0.f = *(const float4*)&As[k][ty * 8];
        F4U a1; a1.f = *(const float4*)&As[k][ty * 8 + 4];
#pragma unroll
        for (int i = 0; i < 8; i++) {
            float av = (i < 4) ? a0.s[i] : a1.s[i - 4];
            u64 a2 = pack2(av, av);
            acc[i][0] = fma2(a2, q.u[0], acc[i][0]);
            acc[i][1] = fma2(a2, q.u[1], acc[i][1]);
        }
    }

    float4 bv = *(const float4*)(bf + tx * 4);
#pragma unroll
    for (int i = 0; i < 8; i++) {
        int row = bm + ty * 8 + i;
        if (row >= NROW) continue;
        F4U o;
        unpack2(acc[i][0], o.s[0], o.s[1]);
        unpack2(acc[i][1], o.s[2], o.s[3]);
        o.s[0] += bv.x; o.s[1] += bv.y; o.s[2] += bv.z; o.s[3] += bv.w;
        if (row < BL) {
            *(float4*)(pk + row * 128 + tx * 4) = o.f;
        } else {
            int item = row - BL;
            pkcT[(tx * 4 + 0) * NIT + item] = o.s[0];
            pkcT[(tx * 4 + 1) * NIT + item] = o.s[1];
            pkcT[(tx * 4 + 2) * NIT + item] = o.s[2];
            pkcT[(tx * 4 + 3) * NIT + item] = o.s[3];
        }
    }
}

// ===========================================================================
// K4: agg heads: catgy (32 blocks) + pd/pdT (4 blocks) + loss (1 block)
// ===========================================================================
__device__ __forceinline__ void gemm64(float (*As)[132], float (*Bs)[68],
                                       const float* __restrict__ A, const float* __restrict__ B,
                                       const float* __restrict__ bias,
                                       float* __restrict__ C, float* __restrict__ CT,
                                       int M, int N, int bm, int bn, int tid) {
    for (int i = tid; i < 64 * 32; i += 256) {
        int r = i >> 5, k4 = (i & 31) * 4;
        float4 v = make_float4(0.f, 0.f, 0.f, 0.f);
        if (bm + r < M) v = *(const float4*)(A + (bm + r) * 128 + k4);
        *(float4*)&As[r][k4] = v;
    }
    for (int i = tid; i < 128 * 16; i += 256) {
        int k = i >> 4, c4 = (i & 15) * 4, c = bn + c4;
        const float* brow = B + k * N;
        float4 v = make_float4(0.f, 0.f, 0.f, 0.f);
        if (c + 3 < N) v = *(const float4*)(brow + c);
        else {
            if (c     < N) v.x = brow[c];
            if (c + 1 < N) v.y = brow[c + 1];
            if (c + 2 < N) v.z = brow[c + 2];
        }
        *(float4*)&Bs[k][c4] = v;
    }
    __syncthreads();
    int tx = tid & 15, ty = tid >> 4;
    float acc[4][4];
#pragma unroll
    for (int i = 0; i < 4; i++)
#pragma unroll
        for (int j = 0; j < 4; j++) acc[i][j] = 0.f;
#pragma unroll 4
    for (int k = 0; k < 128; k++) {
        float a[4], b[4];
#pragma unroll
        for (int i = 0; i < 4; i++) a[i] = As[ty * 4 + i][k];
#pragma unroll
        for (int j = 0; j < 4; j++) b[j] = Bs[k][tx * 4 + j];
#pragma unroll
        for (int i = 0; i < 4; i++)
#pragma unroll
            for (int j = 0; j < 4; j++)
                acc[i][j] = fmaf(a[i], b[j], acc[i][j]);
    }
#pragma unroll
    for (int i = 0; i < 4; i++) {
        int r = bm + ty * 4 + i;
        if (r >= M) break;
#pragma unroll
        for (int j = 0; j < 4; j++) {
            int c = bn + tx * 4 + j;
            if (c < N) {
                float v = acc[i][j] + (bias ? bias[c] : 0.f);
                C[r * N + c] = v;
                if (CT) CT[c * M + r] = v;
            }
        }
    }
}

__global__ void k4_heads(const float* __restrict__ agg,
                         const float* __restrict__ Wc, const float* __restrict__ bc,
                         const float* __restrict__ W1, const float* __restrict__ b1,
                         float* __restrict__ out,
                         float* __restrict__ pd, float* __restrict__ pdT) {
    __shared__ float As[64][132];
    __shared__ float Bs[128][68];
    __shared__ float inv[128];
    __shared__ float redl[128];
    int bx = blockIdx.x, tid = threadIdx.x;
    if (bx < 32) {
        int bm = (bx >> 4) * 64, bn = (bx & 15) * 64;
        gemm64(As, Bs, agg, Wc, bc, out + OFF_CATGY, nullptr, 128, 1000, bm, bn, tid);
    } else if (bx < 36) {
        int l = bx - 32;
        int bm = (l >> 1) * 64, bn = (l & 1) * 64;
        gemm64(As, Bs, agg, W1, b1, pd, pdT, 128, 128, bm, bn, tid);  // W1[:128] = Wd1
    } else {
        // demand_sim_loss
        if (tid < 128) {
            const float* a = agg + tid * 128;
            float s = 0.f;
#pragma unroll 8
            for (int h = 0; h < 128; h++) s = fmaf(a[h], a[h], s);
            inv[tid] = 1.f / (sqrtf(s) + 1e-12f);
        }
        __syncthreads();
        if (tid < 128) {
            float accv = 0.f;
            int h = tid;
            for (int b = 0; b < 16; b++) {
                float sv = 0.f, sq = 0.f;
#pragma unroll
                for (int d = 0; d < 8; d++) {
                    int bd = b * 8 + d;
                    float x = agg[bd * 128 + h] * inv[bd];
                    sv += x;
                    sq = fmaf(x, x, sq);
                }
                accv += sv * sv - sq;
            }
            redl[tid] = accv;
        }
        __syncthreads();
        if (tid == 0) {
            float t = 0.f;
            for (int i = 0; i < 128; i++) t += redl[i];
            out[OFF_LOSS] = t / 896.f;
        }
    }
}

// ===========================================================================
// K5: scores.  blocks 0..127: cand relu-GEMM (64 bd x 128 items, f32x2);
//              blocks 128..227: dscore (one warp per (b,l,d)).
// ===========================================================================
__global__ void k5_scores(const float* __restrict__ pdT, const float* __restrict__ pd,
                          const float* __restrict__ pkcT, const float* __restrict__ pk,
                          const float* __restrict__ w,
                          float* __restrict__ out) {
    __shared__ __align__(16) float Ps[128][68];   // [k][bd]
    __shared__ __align__(16) float Qs[128][132];  // [k][item]
    __shared__ float ws[128];
    int bx = blockIdx.x, tid = threadIdx.x;

    if (bx < 128) {
        int bdb = (bx >> 6) * 64, itb = (bx & 63) * 128;
        for (int idx = tid; idx < 128 * 16; idx += 256) {
            int k = idx >> 4, r4 = idx & 15;
            *(float4*)&Ps[k][r4 * 4] = *(const float4*)(pdT + k * 128 + bdb + r4 * 4);
        }
        for (int idx = tid; idx < 128 * 32; idx += 256) {
            int k = idx >> 5, c4 = idx & 31;
            *(float4*)&Qs[k][c4 * 4] = *(const float4*)(pkcT + k * NIT + itb + c4 * 4);
        }
        if (tid < 128) ws[tid] = w[tid];
        __syncthreads();

        int tx = tid & 15, ty = tid >> 4;   // items tx*8 (4 pairs), bd ty*4
        u64 acc[4][4];
#pragma unroll
        for (int i = 0; i < 4; i++)
#pragma unroll
            for (int p = 0; p < 4; p++) acc[i][p] = 0ull;

#pragma unroll 2
        for (int k = 0; k < 128; k++) {
            F4U a; a.f = *(const float4*)&Ps[k][ty * 4];
            F4U q0; q0.f = *(const float4*)&Qs[k][tx * 8];
            F4U q1; q1.f = *(const float4*)&Qs[k][tx * 8 + 4];
            float wk = ws[k];
            u64 w2 = pack2(wk, wk);
            u64 qp[4] = { q0.u[0], q0.u[1], q1.u[0], q1.u[1] };
#pragma unroll
            for (int i = 0; i < 4; i++) {
                u64 a2 = pack2(a.s[i], a.s[i]);
#pragma unroll
                for (int p = 0; p < 4; p++) {
                    u64 t = relu2(add2(a2, qp[p]));
                    acc[i][p] = fma2(t, w2, acc[i][p]);
                }
            }
        }

#pragma unroll
        for (int i = 0; i < 4; i++) {
            int row = bdb + ty * 4 + i;
            F4U o0, o1;
            o0.u[0] = acc[i][0]; o0.u[1] = acc[i][1];
            o1.u[0] = acc[i][2]; o1.u[1] = acc[i][3];
            float* dst = out + OFF_DCAND + (size_t)row * NIT + itb + tx * 8;
            *(float4*)dst       = o0.f;
            *(float4*)(dst + 4) = o1.f;
        }
    } else {
        // dscore: 100 blocks x 8 warps = 800 warps, one per (b,l); 8 d handled
        int wid  = (bx - 128) * 8 + (tid >> 5);
        int lane = tid & 31;
        if (wid >= 800 * 8 / 8) { /* wid in 0..799 -> (b,l); loop d */ }
        int b = wid / 50, l = wid % 50;
        const float4* k4 = (const float4*)(pk + (b * 50 + l) * 128);
        const float4* w4 = (const float4*)w;
        float4 c = k4[lane], ww = w4[lane];
#pragma unroll
        for (int d = 0; d < 8; d++) {
            const float4* p4 = (const float4*)(pd + (b * 8 + d) * 128);
            float4 a = p4[lane];
            float acc = fmaxf(a.x + c.x, 0.f) * ww.x
                      + fmaxf(a.y + c.y, 0.f) * ww.y
                      + fmaxf(a.z + c.z, 0.f) * ww.z
                      + fmaxf(a.w + c.w, 0.f) * ww.w;
#pragma unroll
            for (int o = 16; o > 0; o >>= 1) acc += __shfl_down_sync(0xffffffffu, acc, o);
            if (lane == 0) out[OFF_DSC + b * 400 + l * 8 + d] = acc;
        }
    }
}

// ===========================================================================
extern "C" void kernel_launch(void* const* d_in, const int* in_sizes, int n_in,
                              void* d_out, int out_size) {
    const int*   input = (const int*)d_in[0];
    const int*   cand  = (const int*)d_in[1];
    const float* table = (const float*)d_in[4];
    const float* Wd    = (const float*)d_in[5];
    const float* Wk    = (const float*)d_in[6];
    const float* bk    = (const float*)d_in[7];
    const float* W1    = (const float*)d_in[8];
    const float* b1    = (const float*)d_in[9];
    const float* wsc   = (const float*)d_in[10];
    const float* Wc    = (const float*)d_in[11];
    const float* bc    = (const float*)d_in[12];
    float* out = (float*)d_out;

    float *wf, *bf, *agg, *pd, *pdT, *pk, *pkcT;
    cudaGetSymbolAddress((void**)&wf,   g_wf);
    cudaGetSymbolAddress((void**)&bf,   g_bf);
    cudaGetSymbolAddress((void**)&agg,  g_agg);
    cudaGetSymbolAddress((void**)&pd,   g_pd);
    cudaGetSymbolAddress((void**)&pdT,  g_pdT);
    cudaGetSymbolAddress((void**)&pk,   g_pk);
    cudaGetSymbolAddress((void**)&pkcT, g_pkcT);

    const float* Wk1 = W1 + 128 * 128;

    k1_prep<<<1189, 256>>>(input, cand, table, Wk, Wk1, bk, out, wf, bf);
    k2_embwd_lse<<<dim3(8, 16), 256>>>(out + OFF_EMB, Wd, agg);
    k3_pkgemm<<<141, 256>>>(out, wf, bf, pk, pkcT);
    k4_heads<<<37, 256>>>(agg, Wc, bc, W1, b1, out, pd, pdT);
    k5_scores<<<228, 256>>>(pdT, pd, pkcT, pk, wsc, out);
}

// round 3
// speedup vs baseline: 1.7311x; 1.1215x over previous
#include <cuda_runtime.h>
#include <math.h>

typedef unsigned long long u64;

// ---- problem constants ----
#define BL    800
#define NIT   8192
#define NROW  8992

// ---- output layout ----
#define OFF_CATGY 0
#define OFF_DSC   128000
#define OFF_DCAND 134400
#define OFF_EMB   1182976
#define OFF_ECAND 1285376
#define OFF_LOSS  2333952

// ---- scratch ----
__device__ float g_wf  [128 * 128];
__device__ float g_bf  [128];
__device__ float g_agg [128 * 128];
__device__ float g_pd  [128 * 128];
__device__ float g_pdT [128 * 128];
__device__ float g_pk  [BL * 128];
__device__ float g_pkcT[128 * NIT];

// ---- f32x2 helpers ----
union F4U { float4 f; u64 u[2]; float s[4]; };

__device__ __forceinline__ u64 pack2(float lo, float hi) {
    u64 r; asm("mov.b64 %0, {%1,%2};" : "=l"(r) : "f"(lo), "f"(hi)); return r;
}
__device__ __forceinline__ void unpack2(u64 v, float& lo, float& hi) {
    asm("mov.b64 {%0,%1}, %2;" : "=f"(lo), "=f"(hi) : "l"(v));
}
__device__ __forceinline__ u64 fma2(u64 a, u64 b, u64 c) {
    u64 r; asm("fma.rn.f32x2 %0, %1, %2, %3;" : "=l"(r) : "l"(a), "l"(b), "l"(c)); return r;
}
__device__ __forceinline__ u64 add2(u64 a, u64 b) {
    u64 r; asm("add.rn.f32x2 %0, %1, %2;" : "=l"(r) : "l"(a), "l"(b)); return r;
}
__device__ __forceinline__ u64 relu2(u64 v) {
    float a, b; unpack2(v, a, b);
    a = fmaxf(a, 0.f); b = fmaxf(b, 0.f);
    return pack2(a, b);
}

// ===========================================================================
// K_A: wf = Wk@Wk1 (64 blocks x 2 rows), bf = bk@Wk1 (block 64)
// ===========================================================================
__global__ void kA_fold(const float* __restrict__ Wk, const float* __restrict__ Wk1,
                        const float* __restrict__ bk,
                        float* __restrict__ wf, float* __restrict__ bf) {
    __shared__ float rw[2][128];
    int bx = blockIdx.x, tid = threadIdx.x;
    if (bx < 64) {
        int r0 = bx * 2;
        rw[tid >> 7][tid & 127] = Wk[r0 * 128 + tid];
        __syncthreads();
        int row = tid >> 7, col = tid & 127;
        float acc = 0.f;
#pragma unroll 8
        for (int h = 0; h < 128; h++)
            acc = fmaf(rw[row][h], __ldg(Wk1 + h * 128 + col), acc);
        wf[(r0 + row) * 128 + col] = acc;
    } else if (tid < 128) {
        float acc = 0.f;
#pragma unroll 8
        for (int h = 0; h < 128; h++)
            acc = fmaf(__ldg(bk + h), __ldg(Wk1 + h * 128 + tid), acc);
        bf[tid] = acc;
    }
}

// ===========================================================================
// K_B: blocks 0..280: pk/pkcT GEMM (gathers rows itself + writes emb/ecand out)
//      blocks 281..536: fused emb@Wd + logsumexp (gathers its own rows)
// ===========================================================================
__global__ void kB_main(const int* __restrict__ inp, const int* __restrict__ cand,
                        const float* __restrict__ table,
                        const float* __restrict__ wf, const float* __restrict__ bf,
                        const float* __restrict__ Wd,
                        float* __restrict__ out,
                        float* __restrict__ pk, float* __restrict__ pkcT,
                        float* __restrict__ agg) {
    __shared__ __align__(16) char sb[106752];
    int bx = blockIdx.x, tid = threadIdx.x;
    const float4* t4 = (const float4*)table;

    if (bx < 281) {
        // ---- pk / pkcT GEMM: 32 rows x 128 cols ----
        u64*   As2 = (u64*)sb;                 // [128][34] dup pairs
        float* Bs  = (float*)(sb + 34816);     // [128][132]
        int bm = bx * 32;

#pragma unroll
        for (int p = 0; p < 4; p++) {
            int i = tid + p * 256;             // 1024 = 32 rows x 32 k4
            int r = i >> 5, k4 = i & 31;
            int row = bm + r;
            int idx = (row < BL) ? inp[row] : cand[row - BL];
            float4 v = t4[idx * 32 + k4];
            float* dst = (row < BL) ? (out + OFF_EMB + row * 128)
                                    : (out + OFF_ECAND + (row - BL) * 128);
            ((float4*)dst)[k4] = v;
            int kb = k4 * 4;
            As2[(kb + 0) * 34 + r] = pack2(v.x, v.x);
            As2[(kb + 1) * 34 + r] = pack2(v.y, v.y);
            As2[(kb + 2) * 34 + r] = pack2(v.z, v.z);
            As2[(kb + 3) * 34 + r] = pack2(v.w, v.w);
        }
#pragma unroll
        for (int p = 0; p < 16; p++) {
            int i = tid + p * 256;             // 4096 = 128 k x 32 j4
            int k = i >> 5, j4 = (i & 31) * 4;
            *(float4*)&Bs[k * 132 + j4] = *(const float4*)(wf + k * 128 + j4);
        }
        __syncthreads();

        int tx = tid & 31, ty = tid >> 5;      // cols tx*4, rows ty*4
        u64 acc[4][2];
#pragma unroll
        for (int i = 0; i < 4; i++) { acc[i][0] = 0ull; acc[i][1] = 0ull; }

#pragma unroll 4
        for (int k = 0; k < 128; k++) {
            F4U a0; a0.f = *(const float4*)&As2[k * 34 + ty * 4];       // rows ty*4, +1
            F4U a1; a1.f = *(const float4*)&As2[k * 34 + ty * 4 + 2];   // rows +2, +3
            F4U q;  q.f  = *(const float4*)&Bs[k * 132 + tx * 4];
            acc[0][0] = fma2(a0.u[0], q.u[0], acc[0][0]);
            acc[0][1] = fma2(a0.u[0], q.u[1], acc[0][1]);
            acc[1][0] = fma2(a0.u[1], q.u[0], acc[1][0]);
            acc[1][1] = fma2(a0.u[1], q.u[1], acc[1][1]);
            acc[2][0] = fma2(a1.u[0], q.u[0], acc[2][0]);
            acc[2][1] = fma2(a1.u[0], q.u[1], acc[2][1]);
            acc[3][0] = fma2(a1.u[1], q.u[0], acc[3][0]);
            acc[3][1] = fma2(a1.u[1], q.u[1], acc[3][1]);
        }

        float4 bv = *(const float4*)(bf + tx * 4);
#pragma unroll
        for (int i = 0; i < 4; i++) {
            int row = bm + ty * 4 + i;
            F4U o; o.u[0] = acc[i][0]; o.u[1] = acc[i][1];
            o.s[0] += bv.x; o.s[1] += bv.y; o.s[2] += bv.z; o.s[3] += bv.w;
            if (row < BL) {
                *(float4*)(pk + row * 128 + tx * 4) = o.f;
            } else {
                int it = row - BL;
                pkcT[(tx * 4 + 0) * NIT + it] = o.s[0];
                pkcT[(tx * 4 + 1) * NIT + it] = o.s[1];
                pkcT[(tx * 4 + 2) * NIT + it] = o.s[2];
                pkcT[(tx * 4 + 3) * NIT + it] = o.s[3];
            }
        }
    } else {
        // ---- fused emb@Wd + logsumexp: batch b, 64-col slab cb ----
        u64*   As2 = (u64*)sb;                 // [128][66] dup pairs (l dim)
        float* Bs  = (float*)(sb + 67584);     // [128][68]
        float* red = (float*)(sb + 102400);    // [16][68]
        int t = bx - 281;
        int b = t >> 4, cb = t & 15;

#pragma unroll
        for (int p = 0; p < 8; p++) {
            int i = tid + p * 256;             // 2048 = 64 l x 32 k4
            int l = i & 63, k4 = i >> 6;
            float4 v = make_float4(0.f, 0.f, 0.f, 0.f);
            if (l < 50) { int idx = inp[b * 50 + l]; v = t4[idx * 32 + k4]; }
            int kb = k4 * 4;
            As2[(kb + 0) * 66 + l] = pack2(v.x, v.x);
            As2[(kb + 1) * 66 + l] = pack2(v.y, v.y);
            As2[(kb + 2) * 66 + l] = pack2(v.z, v.z);
            As2[(kb + 3) * 66 + l] = pack2(v.w, v.w);
        }
#pragma unroll
        for (int p = 0; p < 8; p++) {
            int i = tid + p * 256;             // 2048 = 128 k x 16 c4
            int k = i >> 4, c4 = (i & 15) * 4;
            *(float4*)&Bs[k * 68 + c4] = *(const float4*)(Wd + k * 1024 + cb * 64 + c4);
        }
        __syncthreads();

        int tx = tid & 15, ty = tid >> 4;      // cols tx*4 (64), l rows ty*4 (64)
        u64 acc[4][2];
#pragma unroll
        for (int i = 0; i < 4; i++) { acc[i][0] = 0ull; acc[i][1] = 0ull; }

#pragma unroll 4
        for (int k = 0; k < 128; k++) {
            F4U a0; a0.f = *(const float4*)&As2[k * 66 + ty * 4];
            F4U a1; a1.f = *(const float4*)&As2[k * 66 + ty * 4 + 2];
            F4U q;  q.f  = *(const float4*)&Bs[k * 68 + tx * 4];
            acc[0][0] = fma2(a0.u[0], q.u[0], acc[0][0]);
            acc[0][1] = fma2(a0.u[0], q.u[1], acc[0][1]);
            acc[1][0] = fma2(a0.u[1], q.u[0], acc[1][0]);
            acc[1][1] = fma2(a0.u[1], q.u[1], acc[1][1]);
            acc[2][0] = fma2(a1.u[0], q.u[0], acc[2][0]);
            acc[2][1] = fma2(a1.u[0], q.u[1], acc[2][1]);
            acc[3][0] = fma2(a1.u[1], q.u[0], acc[3][0]);
            acc[3][1] = fma2(a1.u[1], q.u[1], acc[3][1]);
        }

        float vals[4][4];
#pragma unroll
        for (int i = 0; i < 4; i++) {
            unpack2(acc[i][0], vals[i][0], vals[i][1]);
            unpack2(acc[i][1], vals[i][2], vals[i][3]);
        }
        int nval = 50 - ty * 4; if (nval > 4) nval = 4; if (nval < 0) nval = 0;
#pragma unroll
        for (int u = 0; u < 4; u++) {
            float mm = -INFINITY;
            for (int i = 0; i < nval; i++) mm = fmaxf(mm, vals[i][u]);
            red[ty * 68 + tx * 4 + u] = mm;
        }
        __syncthreads();
        float M[4];
#pragma unroll
        for (int u = 0; u < 4; u++) {
            float mm = -INFINITY;
#pragma unroll
            for (int tt = 0; tt < 16; tt++) mm = fmaxf(mm, red[tt * 68 + tx * 4 + u]);
            M[u] = mm;
        }
        __syncthreads();
#pragma unroll
        for (int u = 0; u < 4; u++) {
            float s = 0.f;
            for (int i = 0; i < nval; i++) s += expf(vals[i][u] - M[u]);
            red[ty * 68 + tx * 4 + u] = s;
        }
        __syncthreads();
        if (ty == 0) {
#pragma unroll
            for (int u = 0; u < 4; u++) {
                float S = 0.f;
#pragma unroll
                for (int tt = 0; tt < 16; tt++) S += red[tt * 68 + tx * 4 + u];
                agg[b * 1024 + cb * 64 + tx * 4 + u] = M[u] + logf(S);
            }
        }
    }
}

// ===========================================================================
// K_C: agg heads. blocks 0..63 catgy (32x64), 64..71 pd/pdT (32x64), 72 loss.
// ===========================================================================
__global__ void kC_heads(const float* __restrict__ agg,
                         const float* __restrict__ Wc, const float* __restrict__ bc,
                         const float* __restrict__ W1, const float* __restrict__ b1,
                         float* __restrict__ out,
                         float* __restrict__ pd, float* __restrict__ pdT) {
    __shared__ __align__(16) char sb[70656];
    u64*   As2 = (u64*)sb;                // [128][34]
    float* Bs  = (float*)(sb + 34816);    // [128][68]
    float* aux = (float*)(sb + 69632);    // 256 floats (loss)
    int bx = blockIdx.x, tid = threadIdx.x;

    if (bx < 72) {
        const float* B; const float* bias; float* C; float* CT; int N, bm, bn;
        if (bx < 64) { B = Wc; bias = bc; C = out + OFF_CATGY; CT = nullptr; N = 1000;
                       bm = (bx >> 4) * 32; bn = (bx & 15) * 64; }
        else         { int l = bx - 64; B = W1; bias = b1; C = pd; CT = pdT; N = 128;
                       bm = (l >> 1) * 32; bn = (l & 1) * 64; }

#pragma unroll
        for (int p = 0; p < 4; p++) {
            int i = tid + p * 256;            // 1024 = 32 rows x 32 k4
            int r = i >> 5, k4 = i & 31;
            float4 v = *(const float4*)(agg + (bm + r) * 128 + k4 * 4);
            int kb = k4 * 4;
            As2[(kb + 0) * 34 + r] = pack2(v.x, v.x);
            As2[(kb + 1) * 34 + r] = pack2(v.y, v.y);
            As2[(kb + 2) * 34 + r] = pack2(v.z, v.z);
            As2[(kb + 3) * 34 + r] = pack2(v.w, v.w);
        }
#pragma unroll
        for (int p = 0; p < 8; p++) {
            int i = tid + p * 256;            // 2048 = 128 k x 16 c4
            int k = i >> 4, c4 = (i & 15) * 4;
            int c = bn + c4;
            float4 v = make_float4(0.f, 0.f, 0.f, 0.f);
            const float* brow = B + k * N;
            if (c + 3 < N) v = *(const float4*)(brow + c);
            else {
                if (c     < N) v.x = brow[c];
                if (c + 1 < N) v.y = brow[c + 1];
                if (c + 2 < N) v.z = brow[c + 2];
            }
            *(float4*)&Bs[k * 68 + c4] = v;
        }
        __syncthreads();

        int tx = tid & 15, ty = tid >> 4;     // cols tx*4 (64), rows ty*2 (32)
        u64 acc[2][2];
        acc[0][0] = acc[0][1] = acc[1][0] = acc[1][1] = 0ull;
#pragma unroll 8
        for (int k = 0; k < 128; k++) {
            F4U a; a.f = *(const float4*)&As2[k * 34 + ty * 2];   // rows ty*2, +1
            F4U q; q.f = *(const float4*)&Bs[k * 68 + tx * 4];
            acc[0][0] = fma2(a.u[0], q.u[0], acc[0][0]);
            acc[0][1] = fma2(a.u[0], q.u[1], acc[0][1]);
            acc[1][0] = fma2(a.u[1], q.u[0], acc[1][0]);
            acc[1][1] = fma2(a.u[1], q.u[1], acc[1][1]);
        }

        int c0 = bn + tx * 4;
        float bvx = (c0     < N) ? bias[c0]     : 0.f;
        float bvy = (c0 + 1 < N) ? bias[c0 + 1] : 0.f;
        float bvz = (c0 + 2 < N) ? bias[c0 + 2] : 0.f;
        float bvw = (c0 + 3 < N) ? bias[c0 + 3] : 0.f;
#pragma unroll
        for (int i = 0; i < 2; i++) {
            int r = bm + ty * 2 + i;
            F4U o; o.u[0] = acc[i][0]; o.u[1] = acc[i][1];
            o.s[0] += bvx; o.s[1] += bvy; o.s[2] += bvz; o.s[3] += bvw;
            if (c0 + 3 < N) *(float4*)(C + r * N + c0) = o.f;
            else {
#pragma unroll
                for (int u = 0; u < 4; u++)
                    if (c0 + u < N) C[r * N + c0 + u] = o.s[u];
            }
            if (CT) {
#pragma unroll
                for (int u = 0; u < 4; u++) CT[(c0 + u) * 128 + r] = o.s[u];
            }
        }
    } else {
        float* inv  = aux;
        float* redl = aux + 128;
        if (tid < 128) {
            const float* a = agg + tid * 128;
            float s = 0.f;
#pragma unroll 8
            for (int h = 0; h < 128; h++) s = fmaf(a[h], a[h], s);
            inv[tid] = 1.f / (sqrtf(s) + 1e-12f);
        }
        __syncthreads();
        if (tid < 128) {
            float accv = 0.f;
            for (int b = 0; b < 16; b++) {
                float sv = 0.f, sq = 0.f;
#pragma unroll
                for (int d = 0; d < 8; d++) {
                    float x = agg[(b * 8 + d) * 128 + tid] * inv[b * 8 + d];
                    sv += x; sq = fmaf(x, x, sq);
                }
                accv += sv * sv - sq;
            }
            redl[tid] = accv;
        }
        __syncthreads();
        if (tid == 0) {
            float t = 0.f;
            for (int i = 0; i < 128; i++) t += redl[i];
            out[OFF_LOSS] = t / 896.f;
        }
    }
}

// ===========================================================================
// K_D: blocks 0..127 cand relu-GEMM (64 bd x 128 items); 128..227 dscore.
// ===========================================================================
__global__ void kD_scores(const float* __restrict__ pdT, const float* __restrict__ pd,
                          const float* __restrict__ pkcT, const float* __restrict__ pk,
                          const float* __restrict__ w,
                          float* __restrict__ out) {
    __shared__ __align__(16) char sb[136192];
    int bx = blockIdx.x, tid = threadIdx.x;

    if (bx < 128) {
        u64*   Ps2 = (u64*)sb;                 // [128][66] dup (bd dim 64)
        float* Qs  = (float*)(sb + 67584);     // [128][132]
        u64*   ws2 = (u64*)(sb + 135168);      // [128]
        int bdb = (bx >> 6) * 64, itb = (bx & 63) * 128;

#pragma unroll
        for (int p = 0; p < 8; p++) {
            int i = tid + p * 256;             // 2048 = 128 k x 16 r4
            int k = i >> 4, r4 = (i & 15) * 4;
            float4 v = *(const float4*)(pdT + k * 128 + bdb + r4);
            Ps2[k * 66 + r4 + 0] = pack2(v.x, v.x);
            Ps2[k * 66 + r4 + 1] = pack2(v.y, v.y);
            Ps2[k * 66 + r4 + 2] = pack2(v.z, v.z);
            Ps2[k * 66 + r4 + 3] = pack2(v.w, v.w);
        }
#pragma unroll
        for (int p = 0; p < 16; p++) {
            int i = tid + p * 256;             // 4096 = 128 k x 32 c4
            int k = i >> 5, c4 = (i & 31) * 4;
            *(float4*)&Qs[k * 132 + c4] = *(const float4*)(pkcT + k * NIT + itb + c4);
        }
        if (tid < 128) { float wv = w[tid]; ws2[tid] = pack2(wv, wv); }
        __syncthreads();

        int tx = tid & 15, ty = tid >> 4;      // items tx*8, bd ty*4
        u64 acc[4][4];
#pragma unroll
        for (int i = 0; i < 4; i++)
#pragma unroll
            for (int p = 0; p < 4; p++) acc[i][p] = 0ull;

#pragma unroll 2
        for (int k = 0; k < 128; k++) {
            F4U a0; a0.f = *(const float4*)&Ps2[k * 66 + ty * 4];
            F4U a1; a1.f = *(const float4*)&Ps2[k * 66 + ty * 4 + 2];
            F4U q0; q0.f = *(const float4*)&Qs[k * 132 + tx * 8];
            F4U q1; q1.f = *(const float4*)&Qs[k * 132 + tx * 8 + 4];
            u64 w2 = ws2[k];
            u64 aD[4] = { a0.u[0], a0.u[1], a1.u[0], a1.u[1] };
            u64 qp[4] = { q0.u[0], q0.u[1], q1.u[0], q1.u[1] };
#pragma unroll
            for (int i = 0; i < 4; i++)
#pragma unroll
                for (int p = 0; p < 4; p++) {
                    u64 t = relu2(add2(aD[i], qp[p]));
                    acc[i][p] = fma2(t, w2, acc[i][p]);
                }
        }

#pragma unroll
        for (int i = 0; i < 4; i++) {
            int row = bdb + ty * 4 + i;
            F4U o0, o1;
            o0.u[0] = acc[i][0]; o0.u[1] = acc[i][1];
            o1.u[0] = acc[i][2]; o1.u[1] = acc[i][3];
            float* dst = out + OFF_DCAND + (size_t)row * NIT + itb + tx * 8;
            *(float4*)dst       = o0.f;
            *(float4*)(dst + 4) = o1.f;
        }
    } else {
        int wid  = (bx - 128) * 8 + (tid >> 5);   // 0..799 -> (b,l)
        int lane = tid & 31;
        int b = wid / 50, l = wid % 50;
        const float4* k4 = (const float4*)(pk + (b * 50 + l) * 128);
        const float4* w4 = (const float4*)w;
        float4 c = k4[lane], ww = w4[lane];
#pragma unroll
        for (int d = 0; d < 8; d++) {
            const float4* p4 = (const float4*)(pd + (b * 8 + d) * 128);
            float4 a = p4[lane];
            float acc = fmaxf(a.x + c.x, 0.f) * ww.x
                      + fmaxf(a.y + c.y, 0.f) * ww.y
                      + fmaxf(a.z + c.z, 0.f) * ww.z
                      + fmaxf(a.w + c.w, 0.f) * ww.w;
#pragma unroll
            for (int o = 16; o > 0; o >>= 1) acc += __shfl_down_sync(0xffffffffu, acc, o);
            if (lane == 0) out[OFF_DSC + b * 400 + l * 8 + d] = acc;
        }
    }
}

// ===========================================================================
extern "C" void kernel_launch(void* const* d_in, const int* in_sizes, int n_in,
                              void* d_out, int out_size) {
    const int*   input = (const int*)d_in[0];
    const int*   cand  = (const int*)d_in[1];
    const float* table = (const float*)d_in[4];
    const float* Wd    = (const float*)d_in[5];
    const float* Wk    = (const float*)d_in[6];
    const float* bk    = (const float*)d_in[7];
    const float* W1    = (const float*)d_in[8];
    const float* b1    = (const float*)d_in[9];
    const float* wsc   = (const float*)d_in[10];
    const float* Wc    = (const float*)d_in[11];
    const float* bc    = (const float*)d_in[12];
    float* out = (float*)d_out;

    float *wf, *bf, *agg, *pd, *pdT, *pk, *pkcT;
    cudaGetSymbolAddress((void**)&wf,   g_wf);
    cudaGetSymbolAddress((void**)&bf,   g_bf);
    cudaGetSymbolAddress((void**)&agg,  g_agg);
    cudaGetSymbolAddress((void**)&pd,   g_pd);
    cudaGetSymbolAddress((void**)&pdT,  g_pdT);
    cudaGetSymbolAddress((void**)&pk,   g_pk);
    cudaGetSymbolAddress((void**)&pkcT, g_pkcT);

    const float* Wk1 = W1 + 128 * 128;

    kA_fold  <<<65, 256>>>(Wk, Wk1, bk, wf, bf);
    kB_main  <<<537, 256>>>(input, cand, table, wf, bf, Wd, out, pk, pkcT, agg);
    kC_heads <<<73, 256>>>(agg, Wc, bc, W1, b1, out, pd, pdT);
    kD_scores<<<228, 256>>>(pdT, pd, pkcT, pk, wsc, out);
}

// round 4
// speedup vs baseline: 1.8898x; 1.0917x over previous
#include <cuda_runtime.h>
#include <math.h>

typedef unsigned long long u64;

#define BL    800
#define NIT   8192
#define NROW  8992

#define OFF_CATGY 0
#define OFF_DSC   128000
#define OFF_DCAND 134400
#define OFF_EMB   1182976
#define OFF_ECAND 1285376
#define OFF_LOSS  2333952

__device__ float g_wf  [128 * 128];
__device__ float g_bf  [128];
__device__ float g_agg [128 * 128];
__device__ float g_pd  [128 * 128];
__device__ float g_pdT [128 * 128];
__device__ float g_pk  [BL * 128];
__device__ float g_pkc [NIT * 128];   // row-major now

union F4U { float4 f; u64 u[2]; float s[4]; };

__device__ __forceinline__ u64 pack2(float lo, float hi) {
    u64 r; asm("mov.b64 %0, {%1,%2};" : "=l"(r) : "f"(lo), "f"(hi)); return r;
}
__device__ __forceinline__ void unpack2(u64 v, float& lo, float& hi) {
    asm("mov.b64 {%0,%1}, %2;" : "=f"(lo), "=f"(hi) : "l"(v));
}
__device__ __forceinline__ u64 fma2(u64 a, u64 b, u64 c) {
    u64 r; asm("fma.rn.f32x2 %0, %1, %2, %3;" : "=l"(r) : "l"(a), "l"(b), "l"(c)); return r;
}
__device__ __forceinline__ u64 add2(u64 a, u64 b) {
    u64 r; asm("add.rn.f32x2 %0, %1, %2;" : "=l"(r) : "l"(a), "l"(b)); return r;
}
__device__ __forceinline__ u64 relu2(u64 v) {
    float a, b; unpack2(v, a, b);
    a = fmaxf(a, 0.f); b = fmaxf(b, 0.f);
    return pack2(a, b);
}

// ===========================================================================
// K1: blocks 0..255  : fused emb@Wd + logsumexp  (b = bx>>4, 64-col slab bx&15)
//     blocks 256..319: wf = Wk@Wk1 (2 rows each)
//     block  320     : bf = bk@Wk1
// ===========================================================================
__global__ void k1_lse_fold(const int* __restrict__ inp,
                            const float* __restrict__ table,
                            const float* __restrict__ Wd,
                            const float* __restrict__ Wk,
                            const float* __restrict__ Wk1,
                            const float* __restrict__ bk,
                            float* __restrict__ agg,
                            float* __restrict__ wf, float* __restrict__ bf) {
    __shared__ __align__(16) char sb[102400];
    int bx = blockIdx.x, tid = threadIdx.x;

    if (bx < 256) {
        u64*   As2 = (u64*)sb;                 // [128][66] dup pairs (l rows)
        float* Bs  = (float*)(sb + 67584);     // [128][68]
        float* red = (float*)(sb + 67584);     // reuse after k-loop [16][68]
        int b = bx >> 4, cb = bx & 15;
        const float4* t4 = (const float4*)table;

#pragma unroll
        for (int p = 0; p < 8; p++) {
            int i = tid + p * 256;             // 2048 = 64 l x 32 k4
            int l = i & 63, k4 = i >> 6;
            float4 v = make_float4(0.f, 0.f, 0.f, 0.f);
            if (l < 50) { int idx = inp[b * 50 + l]; v = t4[idx * 32 + k4]; }
            int kb = k4 * 4;
            As2[(kb + 0) * 66 + l] = pack2(v.x, v.x);
            As2[(kb + 1) * 66 + l] = pack2(v.y, v.y);
            As2[(kb + 2) * 66 + l] = pack2(v.z, v.z);
            As2[(kb + 3) * 66 + l] = pack2(v.w, v.w);
        }
#pragma unroll
        for (int p = 0; p < 8; p++) {
            int i = tid + p * 256;             // 2048 = 128 k x 16 c4
            int k = i >> 4, c4 = (i & 15) * 4;
            *(float4*)&Bs[k * 68 + c4] = *(const float4*)(Wd + k * 1024 + cb * 64 + c4);
        }
        __syncthreads();

        int tx = tid & 15, ty = tid >> 4;      // cols tx*4 (64), rows ty*4 (64)
        u64 acc[4][2];
#pragma unroll
        for (int i = 0; i < 4; i++) { acc[i][0] = 0ull; acc[i][1] = 0ull; }

#pragma unroll 4
        for (int k = 0; k < 128; k++) {
            F4U a0; a0.f = *(const float4*)&As2[k * 66 + ty * 4];
            F4U a1; a1.f = *(const float4*)&As2[k * 66 + ty * 4 + 2];
            F4U q;  q.f  = *(const float4*)&Bs[k * 68 + tx * 4];
            acc[0][0] = fma2(a0.u[0], q.u[0], acc[0][0]);
            acc[0][1] = fma2(a0.u[0], q.u[1], acc[0][1]);
            acc[1][0] = fma2(a0.u[1], q.u[0], acc[1][0]);
            acc[1][1] = fma2(a0.u[1], q.u[1], acc[1][1]);
            acc[2][0] = fma2(a1.u[0], q.u[0], acc[2][0]);
            acc[2][1] = fma2(a1.u[0], q.u[1], acc[2][1]);
            acc[3][0] = fma2(a1.u[1], q.u[0], acc[3][0]);
            acc[3][1] = fma2(a1.u[1], q.u[1], acc[3][1]);
        }

        float vals[4][4];
#pragma unroll
        for (int i = 0; i < 4; i++) {
            unpack2(acc[i][0], vals[i][0], vals[i][1]);
            unpack2(acc[i][1], vals[i][2], vals[i][3]);
        }
        int nval = 50 - ty * 4; if (nval > 4) nval = 4; if (nval < 0) nval = 0;

        __syncthreads();                        // done with Bs/As2
#pragma unroll
        for (int u = 0; u < 4; u++) {
            float mm = -INFINITY;
            for (int i = 0; i < nval; i++) mm = fmaxf(mm, vals[i][u]);
            red[ty * 68 + tx * 4 + u] = mm;
        }
        __syncthreads();
        float M[4];
#pragma unroll
        for (int u = 0; u < 4; u++) {
            float mm = -INFINITY;
#pragma unroll
            for (int t = 0; t < 16; t++) mm = fmaxf(mm, red[t * 68 + tx * 4 + u]);
            M[u] = mm;
        }
        __syncthreads();
#pragma unroll
        for (int u = 0; u < 4; u++) {
            float s = 0.f;
            for (int i = 0; i < nval; i++) s += expf(vals[i][u] - M[u]);
            red[ty * 68 + tx * 4 + u] = s;
        }
        __syncthreads();
        if (ty == 0) {
#pragma unroll
            for (int u = 0; u < 4; u++) {
                float S = 0.f;
#pragma unroll
                for (int t = 0; t < 16; t++) S += red[t * 68 + tx * 4 + u];
                agg[b * 1024 + cb * 64 + tx * 4 + u] = M[u] + logf(S);
            }
        }
    } else if (bx < 320) {
        float* rw = (float*)sb;                // [2][128]
        int r0 = (bx - 256) * 2;
        rw[tid] = Wk[r0 * 128 + tid];
        __syncthreads();
        int row = tid >> 7, col = tid & 127;
        float acc = 0.f;
#pragma unroll 8
        for (int h = 0; h < 128; h++)
            acc = fmaf(rw[row * 128 + h], __ldg(Wk1 + h * 128 + col), acc);
        wf[(r0 + row) * 128 + col] = acc;
    } else {
        if (tid < 128) {
            float acc = 0.f;
#pragma unroll 8
            for (int h = 0; h < 128; h++)
                acc = fmaf(__ldg(bk + h), __ldg(Wk1 + h * 128 + tid), acc);
            bf[tid] = acc;
        }
    }
}

// ===========================================================================
// K2: blocks 0..280  : pk/pkc GEMM (32 rows x 128 cols), gathers + emb out
//     blocks 281..352: agg heads (catgy 64, pd/pdT 8)
//     block  353     : demand_sim_loss
// ===========================================================================
__global__ void k2_gemm_heads(const int* __restrict__ inp, const int* __restrict__ cand,
                              const float* __restrict__ table,
                              const float* __restrict__ wf, const float* __restrict__ bf,
                              const float* __restrict__ agg,
                              const float* __restrict__ Wc, const float* __restrict__ bc,
                              const float* __restrict__ W1, const float* __restrict__ b1,
                              float* __restrict__ out,
                              float* __restrict__ pk, float* __restrict__ pkc,
                              float* __restrict__ pd, float* __restrict__ pdT) {
    __shared__ __align__(16) char sb[102400];
    int bx = blockIdx.x, tid = threadIdx.x;

    if (bx < 281) {
        u64*   As2 = (u64*)sb;                 // [128][34]
        float* Bs  = (float*)(sb + 34816);     // [128][132]
        int bm = bx * 32;
        const float4* t4 = (const float4*)table;

#pragma unroll
        for (int p = 0; p < 4; p++) {
            int i = tid + p * 256;             // 1024 = 32 rows x 32 k4
            int r = i >> 5, k4 = i & 31;
            int row = bm + r;
            int idx = (row < BL) ? inp[row] : cand[row - BL];
            float4 v = t4[idx * 32 + k4];
            float* dst = (row < BL) ? (out + OFF_EMB + row * 128)
                                    : (out + OFF_ECAND + (row - BL) * 128);
            ((float4*)dst)[k4] = v;
            int kb = k4 * 4;
            As2[(kb + 0) * 34 + r] = pack2(v.x, v.x);
            As2[(kb + 1) * 34 + r] = pack2(v.y, v.y);
            As2[(kb + 2) * 34 + r] = pack2(v.z, v.z);
            As2[(kb + 3) * 34 + r] = pack2(v.w, v.w);
        }
#pragma unroll
        for (int p = 0; p < 16; p++) {
            int i = tid + p * 256;             // 4096 = 128 k x 32 j4
            int k = i >> 5, j4 = (i & 31) * 4;
            *(float4*)&Bs[k * 132 + j4] = *(const float4*)(wf + k * 128 + j4);
        }
        __syncthreads();

        int tx = tid & 31, ty = tid >> 5;      // cols tx*4, rows ty*4
        u64 acc[4][2];
#pragma unroll
        for (int i = 0; i < 4; i++) { acc[i][0] = 0ull; acc[i][1] = 0ull; }

#pragma unroll 4
        for (int k = 0; k < 128; k++) {
            F4U a0; a0.f = *(const float4*)&As2[k * 34 + ty * 4];
            F4U a1; a1.f = *(const float4*)&As2[k * 34 + ty * 4 + 2];
            F4U q;  q.f  = *(const float4*)&Bs[k * 132 + tx * 4];
            acc[0][0] = fma2(a0.u[0], q.u[0], acc[0][0]);
            acc[0][1] = fma2(a0.u[0], q.u[1], acc[0][1]);
            acc[1][0] = fma2(a0.u[1], q.u[0], acc[1][0]);
            acc[1][1] = fma2(a0.u[1], q.u[1], acc[1][1]);
            acc[2][0] = fma2(a1.u[0], q.u[0], acc[2][0]);
            acc[2][1] = fma2(a1.u[0], q.u[1], acc[2][1]);
            acc[3][0] = fma2(a1.u[1], q.u[0], acc[3][0]);
            acc[3][1] = fma2(a1.u[1], q.u[1], acc[3][1]);
        }

        float4 bv = *(const float4*)(bf + tx * 4);
#pragma unroll
        for (int i = 0; i < 4; i++) {
            int row = bm + ty * 4 + i;
            F4U o; o.u[0] = acc[i][0]; o.u[1] = acc[i][1];
            o.s[0] += bv.x; o.s[1] += bv.y; o.s[2] += bv.z; o.s[3] += bv.w;
            if (row < BL) *(float4*)(pk  + row * 128 + tx * 4) = o.f;
            else          *(float4*)(pkc + (row - BL) * 128 + tx * 4) = o.f;
        }
    } else if (bx < 353) {
        u64*   As2 = (u64*)sb;                 // [128][34]
        float* Bs  = (float*)(sb + 34816);     // [128][68]
        int hb = bx - 281;
        const float* B; const float* bias; float* C; float* CT; int N, bm, bn;
        if (hb < 64) { B = Wc; bias = bc; C = out + OFF_CATGY; CT = nullptr; N = 1000;
                       bm = (hb >> 4) * 32; bn = (hb & 15) * 64; }
        else         { int l = hb - 64; B = W1; bias = b1; C = pd; CT = pdT; N = 128;
                       bm = (l >> 1) * 32; bn = (l & 1) * 64; }

#pragma unroll
        for (int p = 0; p < 4; p++) {
            int i = tid + p * 256;
            int r = i >> 5, k4 = i & 31;
            float4 v = *(const float4*)(agg + (bm + r) * 128 + k4 * 4);
            int kb = k4 * 4;
            As2[(kb + 0) * 34 + r] = pack2(v.x, v.x);
            As2[(kb + 1) * 34 + r] = pack2(v.y, v.y);
            As2[(kb + 2) * 34 + r] = pack2(v.z, v.z);
            As2[(kb + 3) * 34 + r] = pack2(v.w, v.w);
        }
#pragma unroll
        for (int p = 0; p < 8; p++) {
            int i = tid + p * 256;
            int k = i >> 4, c4 = (i & 15) * 4;
            int c = bn + c4;
            float4 v = make_float4(0.f, 0.f, 0.f, 0.f);
            const float* brow = B + k * N;
            if (c + 3 < N) v = *(const float4*)(brow + c);
            else {
                if (c     < N) v.x = brow[c];
                if (c + 1 < N) v.y = brow[c + 1];
                if (c + 2 < N) v.z = brow[c + 2];
            }
            *(float4*)&Bs[k * 68 + c4] = v;
        }
        __syncthreads();

        int tx = tid & 15, ty = tid >> 4;      // cols tx*4 (64), rows ty*2 (32)
        u64 acc[2][2];
        acc[0][0] = acc[0][1] = acc[1][0] = acc[1][1] = 0ull;
#pragma unroll 8
        for (int k = 0; k < 128; k++) {
            F4U a; a.f = *(const float4*)&As2[k * 34 + ty * 2];
            F4U q; q.f = *(const float4*)&Bs[k * 68 + tx * 4];
            acc[0][0] = fma2(a.u[0], q.u[0], acc[0][0]);
            acc[0][1] = fma2(a.u[0], q.u[1], acc[0][1]);
            acc[1][0] = fma2(a.u[1], q.u[0], acc[1][0]);
            acc[1][1] = fma2(a.u[1], q.u[1], acc[1][1]);
        }

        int c0 = bn + tx * 4;
        float bvx = (c0     < N) ? bias[c0]     : 0.f;
        float bvy = (c0 + 1 < N) ? bias[c0 + 1] : 0.f;
        float bvz = (c0 + 2 < N) ? bias[c0 + 2] : 0.f;
        float bvw = (c0 + 3 < N) ? bias[c0 + 3] : 0.f;
#pragma unroll
        for (int i = 0; i < 2; i++) {
            int r = bm + ty * 2 + i;
            F4U o; o.u[0] = acc[i][0]; o.u[1] = acc[i][1];
            o.s[0] += bvx; o.s[1] += bvy; o.s[2] += bvz; o.s[3] += bvw;
            if (c0 + 3 < N) *(float4*)(C + r * N + c0) = o.f;
            else {
#pragma unroll
                for (int u = 0; u < 4; u++)
                    if (c0 + u < N) C[r * N + c0 + u] = o.s[u];
            }
            if (CT) {
#pragma unroll
                for (int u = 0; u < 4; u++) CT[(c0 + u) * 128 + r] = o.s[u];
            }
        }
    } else {
        float* inv  = (float*)sb;
        float* redl = (float*)sb + 128;
        if (tid < 128) {
            const float* a = agg + tid * 128;
            float s = 0.f;
#pragma unroll 8
            for (int h = 0; h < 128; h++) s = fmaf(a[h], a[h], s);
            inv[tid] = 1.f / (sqrtf(s) + 1e-12f);
        }
        __syncthreads();
        if (tid < 128) {
            float accv = 0.f;
            for (int b = 0; b < 16; b++) {
                float sv = 0.f, sq = 0.f;
#pragma unroll
                for (int d = 0; d < 8; d++) {
                    float x = agg[(b * 8 + d) * 128 + tid] * inv[b * 8 + d];
                    sv += x; sq = fmaf(x, x, sq);
                }
                accv += sv * sv - sq;
            }
            redl[tid] = accv;
        }
        __syncthreads();
        if (tid == 0) {
            float t = 0.f;
            for (int i = 0; i < 128; i++) t += redl[i];
            out[OFF_LOSS] = t / 896.f;
        }
    }
}

// ===========================================================================
// K3: blocks 0..255 : cand relu-GEMM, 64 bd x 64 items
//     blocks 256..295: dscore (320 warps, ~2.5 (b,l) each)
// ===========================================================================
__global__ void k3_scores(const float* __restrict__ pdT, const float* __restrict__ pd,
                          const float* __restrict__ pkc, const float* __restrict__ pk,
                          const float* __restrict__ w,
                          float* __restrict__ out) {
    __shared__ __align__(16) char sb[103424];
    int bx = blockIdx.x, tid = threadIdx.x;

    if (bx < 256) {
        u64*   Ps2 = (u64*)sb;                 // [128][66] dup (bd)
        float* Qs  = (float*)(sb + 67584);     // [128][68] (items, k-major)
        u64*   ws2 = (u64*)(sb + 102400);      // [128]
        int bdb = (bx >> 7) * 64, itb = (bx & 127) * 64;

#pragma unroll
        for (int p = 0; p < 8; p++) {
            int i = tid + p * 256;             // 2048 = 128 k x 16 r4
            int k = i >> 4, r4 = (i & 15) * 4;
            float4 v = *(const float4*)(pdT + k * 128 + bdb + r4);
            Ps2[k * 66 + r4 + 0] = pack2(v.x, v.x);
            Ps2[k * 66 + r4 + 1] = pack2(v.y, v.y);
            Ps2[k * 66 + r4 + 2] = pack2(v.z, v.z);
            Ps2[k * 66 + r4 + 3] = pack2(v.w, v.w);
        }
#pragma unroll
        for (int p = 0; p < 8; p++) {
            int i = tid + p * 256;             // 2048 = 64 it x 32 k4 (transpose load)
            int itl = i & 63, k4 = i >> 6;
            float4 v = *(const float4*)(pkc + (itb + itl) * 128 + k4 * 4);
            int kb = k4 * 4;
            Qs[(kb + 0) * 68 + itl] = v.x;
            Qs[(kb + 1) * 68 + itl] = v.y;
            Qs[(kb + 2) * 68 + itl] = v.z;
            Qs[(kb + 3) * 68 + itl] = v.w;
        }
        if (tid < 128) { float wv = w[tid]; ws2[tid] = pack2(wv, wv); }
        __syncthreads();

        int tx = tid & 15, ty = tid >> 4;      // items tx*4 (2 u64), bd ty*4
        u64 acc[4][2];
#pragma unroll
        for (int i = 0; i < 4; i++) { acc[i][0] = 0ull; acc[i][1] = 0ull; }

#pragma unroll 2
        for (int k = 0; k < 128; k++) {
            F4U a0; a0.f = *(const float4*)&Ps2[k * 66 + ty * 4];
            F4U a1; a1.f = *(const float4*)&Ps2[k * 66 + ty * 4 + 2];
            F4U q;  q.f  = *(const float4*)&Qs[k * 68 + tx * 4];
            u64 w2 = ws2[k];
            u64 aD[4] = { a0.u[0], a0.u[1], a1.u[0], a1.u[1] };
#pragma unroll
            for (int i = 0; i < 4; i++) {
#pragma unroll
                for (int p = 0; p < 2; p++) {
                    u64 t = relu2(add2(aD[i], q.u[p]));
                    acc[i][p] = fma2(t, w2, acc[i][p]);
                }
            }
        }

#pragma unroll
        for (int i = 0; i < 4; i++) {
            int row = bdb + ty * 4 + i;
            F4U o; o.u[0] = acc[i][0]; o.u[1] = acc[i][1];
            *(float4*)(out + OFF_DCAND + (size_t)row * NIT + itb + tx * 4) = o.f;
        }
    } else {
        int wid0 = (bx - 256) * 8 + (tid >> 5);   // 0..319
        int lane = tid & 31;
        const float4* w4 = (const float4*)w;
        float4 ww = w4[lane];
#pragma unroll
        for (int rep = 0; rep < 3; rep++) {
            int wid = wid0 + rep * 320;
            if (wid >= 800) break;
            int b = wid / 50, l = wid % 50;
            const float4* k4 = (const float4*)(pk + (b * 50 + l) * 128);
            float4 c = k4[lane];
#pragma unroll
            for (int d = 0; d < 8; d++) {
                const float4* p4 = (const float4*)(pd + (b * 8 + d) * 128);
                float4 a = p4[lane];
                float acc = fmaxf(a.x + c.x, 0.f) * ww.x
                          + fmaxf(a.y + c.y, 0.f) * ww.y
                          + fmaxf(a.z + c.z, 0.f) * ww.z
                          + fmaxf(a.w + c.w, 0.f) * ww.w;
#pragma unroll
                for (int o = 16; o > 0; o >>= 1) acc += __shfl_down_sync(0xffffffffu, acc, o);
                if (lane == 0) out[OFF_DSC + b * 400 + l * 8 + d] = acc;
            }
        }
    }
}

// ===========================================================================
extern "C" void kernel_launch(void* const* d_in, const int* in_sizes, int n_in,
                              void* d_out, int out_size) {
    const int*   input = (const int*)d_in[0];
    const int*   cand  = (const int*)d_in[1];
    const float* table = (const float*)d_in[4];
    const float* Wd    = (const float*)d_in[5];
    const float* Wk    = (const float*)d_in[6];
    const float* bk    = (const float*)d_in[7];
    const float* W1    = (const float*)d_in[8];
    const float* b1    = (const float*)d_in[9];
    const float* wsc   = (const float*)d_in[10];
    const float* Wc    = (const float*)d_in[11];
    const float* bc    = (const float*)d_in[12];
    float* out = (float*)d_out;

    float *wf, *bf, *agg, *pd, *pdT, *pk, *pkc;
    cudaGetSymbolAddress((void**)&wf,  g_wf);
    cudaGetSymbolAddress((void**)&bf,  g_bf);
    cudaGetSymbolAddress((void**)&agg, g_agg);
    cudaGetSymbolAddress((void**)&pd,  g_pd);
    cudaGetSymbolAddress((void**)&pdT, g_pdT);
    cudaGetSymbolAddress((void**)&pk,  g_pk);
    cudaGetSymbolAddress((void**)&pkc, g_pkc);

    const float* Wk1 = W1 + 128 * 128;

    k1_lse_fold  <<<321, 256>>>(input, table, Wd, Wk, Wk1, bk, agg, wf, bf);
    k2_gemm_heads<<<354, 256>>>(input, cand, table, wf, bf, agg,
                                Wc, bc, W1, b1, out, pk, pkc, pd, pdT);
    k3_scores    <<<296, 256>>>(pdT, pd, pkc, pk, wsc, out);
}